// round 12
// baseline (speedup 1.0000x reference)
#include <cuda_runtime.h>

#define NN  100000
#define NE  1600000
#define IN_DIM  64
#define HID_DIM 48
#define OUT_DIM 32

#define SCAN_B 512
#define SCAN_NBLK ((NN + SCAN_B - 1) / SCAN_B)

// ---------------------------------------------------------------------------
// Scratch (device globals)
// ---------------------------------------------------------------------------
__device__ float g_h0  [(size_t)NN * HID_DIM];   // (x @ W1) * dis[row]   (pre-scaled)
__device__ float g_out1[(size_t)NN * HID_DIM];   // layer-1 output
__device__ float g_h1  [(size_t)NN * OUT_DIM];   // (relu(out1) @ W2) * dis[row]
__device__ float g_dis [NN];
__device__ int2  g_edge[NE];                     // parsed (src, dst)
__device__ int   g_slot[NE];                     // slot of edge within dst's list
__device__ int   g_esrc[NE];                     // CSR records: src only
__device__ int   g_cnt [NN];
__device__ int   g_rowptr[NN + 1];
__device__ int   g_tstat[SCAN_NBLK];             // lookback: (sum<<2)|status
__device__ int   g_is64;

// ---------------------------------------------------------------------------
// Zero counters + warp-parallel dtype detect (block 0, warp 0):
// int64 values < 2^31 ==> all odd int32 words zero. 32 parallel probes.
// ---------------------------------------------------------------------------
__global__ void k_zero(const int* __restrict__ raw, int n) {
    int i = blockIdx.x * blockDim.x + threadIdx.x;
    if (i < n) g_cnt[i] = 0;
    if (i < SCAN_NBLK) g_tstat[i] = 0;
    if (blockIdx.x == 0 && threadIdx.x < 32) {
        int w = raw[threadIdx.x * 2 + 1];                 // odd int32 words
        unsigned nz = __ballot_sync(0xFFFFFFFFu, w != 0);
        if (threadIdx.x == 0) g_is64 = (nz == 0u);
    }
}

// Parse raw edges -> int2, count in-degrees, record slot within dst's list.
// 2 edges per thread (16B loads).
__global__ void k_convert(const void* __restrict__ raw, int e) {
    int i = (blockIdx.x * blockDim.x + threadIdx.x) * 2;
    if (i >= e) return;
    int s0, d0, s1, d1;
    if (g_is64) {
        const longlong2* ps = (const longlong2*)raw;              // src pairs
        const longlong2* pd = (const longlong2*)((const long long*)raw + e);
        longlong2 sv = ps[i >> 1];
        longlong2 dv = pd[i >> 1];
        s0 = (int)sv.x; s1 = (int)sv.y;
        d0 = (int)dv.x; d1 = (int)dv.y;
    } else {
        const int2* ps = (const int2*)raw;
        const int2* pd = (const int2*)((const int*)raw + e);
        int2 sv = ps[i >> 1];
        int2 dv = pd[i >> 1];
        s0 = sv.x; s1 = sv.y;
        d0 = dv.x; d1 = dv.y;
    }
    s0 = min(max(s0, 0), NN - 1); d0 = min(max(d0, 0), NN - 1);
    g_edge[i] = make_int2(s0, d0);
    g_slot[i] = atomicAdd(&g_cnt[d0], 1);
    if (i + 1 < e) {
        s1 = min(max(s1, 0), NN - 1); d1 = min(max(d1, 0), NN - 1);
        g_edge[i + 1] = make_int2(s1, d1);
        g_slot[i + 1] = atomicAdd(&g_cnt[d1], 1);
    }
}

// ---------------------------------------------------------------------------
// Single-pass exclusive scan of g_cnt -> g_rowptr (decoupled lookback),
// with dis computed in the same pass. status: 0=none, 1=aggregate, 2=prefix.
// ---------------------------------------------------------------------------
__global__ void k_scan(int n, int e) {
    __shared__ int sh[SCAN_B];
    __shared__ int s_prev;
    int bid = blockIdx.x;
    int i = bid * SCAN_B + threadIdx.x;
    int v = (i < n) ? g_cnt[i] : 0;
    if (i < n) g_dis[i] = rsqrtf((float)(v + 1));          // +1 self-loop
    sh[threadIdx.x] = v;
    __syncthreads();
#pragma unroll
    for (int off = 1; off < SCAN_B; off <<= 1) {
        int t = (threadIdx.x >= off) ? sh[threadIdx.x - off] : 0;
        __syncthreads();
        sh[threadIdx.x] += t;
        __syncthreads();
    }
    int total = sh[SCAN_B - 1];

    if (threadIdx.x == 0) {
        if (bid == 0) {
            atomicExch(&g_tstat[0], (total << 2) | 2);     // inclusive prefix ready
            s_prev = 0;
        } else {
            atomicExch(&g_tstat[bid], (total << 2) | 1);   // aggregate ready
            int ex = 0;
            int j = bid - 1;
            while (true) {                                 // predecessors dispatched first
                int w;
                do { w = atomicAdd(&g_tstat[j], 0); } while ((w & 3) == 0);
                ex += (w >> 2);
                if ((w & 3) == 2) break;
                j--;
            }
            s_prev = ex;
            atomicExch(&g_tstat[bid], ((ex + total) << 2) | 2);
        }
    }
    __syncthreads();
    if (i < n) g_rowptr[i] = s_prev + sh[threadIdx.x] - v; // exclusive
    if (i == 0) g_rowptr[n] = e;
}

// ---------------------------------------------------------------------------
// CSR fill, atomic-free: position = rowptr[dst] + precomputed slot.
// ---------------------------------------------------------------------------
__global__ void k_fill(int e) {
    int i = blockIdx.x * blockDim.x + threadIdx.x;
    if (i >= e) return;
    int2 ed = g_edge[i];
    g_esrc[g_rowptr[ed.y] + g_slot[i]] = ed.x;
}

// ---------------------------------------------------------------------------
// Dense transform with pre-scale epilogue:
//   H[r,f] = ((relu?)(X[r,:]) @ W[:,f]) * dis[r]
// ---------------------------------------------------------------------------
template <int K, int F, bool RELU_IN>
__global__ void k_gemm(const float* __restrict__ X,
                       const float* __restrict__ W,
                       float* __restrict__ H, int n) {
    constexpr int G = F / 4;
    __shared__ float Ws[K * F];
    for (int i = threadIdx.x; i < K * F; i += blockDim.x) Ws[i] = W[i];
    __syncthreads();

    int tid = blockIdx.x * blockDim.x + threadIdx.x;
    int row = tid / G;
    int g   = tid % G;
    if (row >= n) return;

    const float* xr = X + (size_t)row * K;
    float4 acc = make_float4(0.f, 0.f, 0.f, 0.f);
#pragma unroll
    for (int k = 0; k < K; k++) {
        float xv = xr[k];
        if (RELU_IN) xv = fmaxf(xv, 0.f);
        float4 w = *reinterpret_cast<const float4*>(&Ws[k * F + g * 4]);
        acc.x = fmaf(xv, w.x, acc.x);
        acc.y = fmaf(xv, w.y, acc.y);
        acc.z = fmaf(xv, w.z, acc.z);
        acc.w = fmaf(xv, w.w, acc.w);
    }
    float ds = g_dis[row];
    acc.x *= ds; acc.y *= ds; acc.z *= ds; acc.w *= ds;
    *reinterpret_cast<float4*>(&H[(size_t)row * F + g * 4]) = acc;
}

// ---------------------------------------------------------------------------
// CSR gather-aggregate with factored normalization:
//   O[v,f] = b[f] + dis[v] * ( Hs[v,f] + sum_{s in list(v)} Hs[s,f] )
// ---------------------------------------------------------------------------
template <int F>
__global__ void k_aggcsr(const float* __restrict__ H,
                         const float* __restrict__ b,
                         float* __restrict__ O, int n) {
    constexpr int G = F / 4;
    int tid = blockIdx.x * blockDim.x + threadIdx.x;
    int node = tid / G;
    int g    = tid % G;
    if (node >= n) return;

    size_t o = (size_t)node * F + g * 4;
    float4 acc = *reinterpret_cast<const float4*>(&H[o]);   // self term (pre-scaled)

    int beg = g_rowptr[node];
    int end = g_rowptr[node + 1];
#pragma unroll 2
    for (int j = beg; j < end; j++) {
        int s = g_esrc[j];                          // broadcast across G threads
        float4 v = *reinterpret_cast<const float4*>(&H[(size_t)s * F + g * 4]);
        acc.x += v.x; acc.y += v.y; acc.z += v.z; acc.w += v.w;
    }
    float ds = g_dis[node];
    float4 bv = *reinterpret_cast<const float4*>(&b[g * 4]);
    float4 ov = make_float4(bv.x + acc.x * ds, bv.y + acc.y * ds,
                            bv.z + acc.z * ds, bv.w + acc.w * ds);
    *reinterpret_cast<float4*>(&O[o]) = ov;
}

// ---------------------------------------------------------------------------
// Launch (8 launches, single stream)
// ---------------------------------------------------------------------------
static inline int cdiv(long long a, int b) { return (int)((a + b - 1) / b); }

extern "C" void kernel_launch(void* const* d_in, const int* in_sizes, int n_in,
                              void* d_out, int out_size) {
    const float* x   = (const float*)d_in[0];
    const void*  ei  = d_in[1];
    const float* W1  = (const float*)d_in[2];
    const float* b1  = (const float*)d_in[3];
    const float* W2  = (const float*)d_in[4];
    const float* b2  = (const float*)d_in[5];
    float*       out = (float*)d_out;

    const int n = in_sizes[0] / IN_DIM;   // 100000
    const int e = in_sizes[1] / 2;        // 1600000

    float *h0, *out1, *h1;
    cudaGetSymbolAddress((void**)&h0,   g_h0);
    cudaGetSymbolAddress((void**)&out1, g_out1);
    cudaGetSymbolAddress((void**)&h1,   g_h1);

    const int T = 256;

    // CSR build (4 launches)
    k_zero   <<<cdiv(n, T), T>>>((const int*)ei, n);
    k_convert<<<cdiv(cdiv(e, 2), T), T>>>(ei, e);
    k_scan   <<<SCAN_NBLK, SCAN_B>>>(n, e);
    k_fill   <<<cdiv(e, T), T>>>(e);

    // Layer 1
    k_gemm<IN_DIM, HID_DIM, false><<<cdiv((long long)n * (HID_DIM / 4), T), T>>>(x, W1, h0, n);
    k_aggcsr<HID_DIM><<<cdiv((long long)n * (HID_DIM / 4), T), T>>>(h0, b1, out1, n);

    // Layer 2
    k_gemm<HID_DIM, OUT_DIM, true><<<cdiv((long long)n * (OUT_DIM / 4), T), T>>>(out1, W2, h1, n);
    k_aggcsr<OUT_DIM><<<cdiv((long long)n * (OUT_DIM / 4), T), T>>>(h1, b2, out, n);
}

// round 15
// speedup vs baseline: 1.0422x; 1.0422x over previous
#include <cuda_runtime.h>

#define NN  100000
#define NE  1600000
#define IN_DIM  64
#define HID_DIM 48
#define OUT_DIM 32

#define SCAN_B 512
#define SCAN_NBLK ((NN + SCAN_B - 1) / SCAN_B)

// ---------------------------------------------------------------------------
// Scratch (device globals)
// ---------------------------------------------------------------------------
__device__ float g_h0  [(size_t)NN * HID_DIM];   // (x @ W1) * dis[row]   (pre-scaled)
__device__ float g_out1[(size_t)NN * HID_DIM];   // layer-1 output
__device__ float g_h1  [(size_t)NN * OUT_DIM];   // (relu(out1) @ W2) * dis[row]
__device__ float g_dis [NN];
__device__ int2  g_edge[NE];                     // parsed (src, dst)
__device__ int   g_slot[NE];                     // slot of edge within dst's list
__device__ int   g_esrc[NE];                     // CSR records: src only
__device__ int   g_cnt [NN];
__device__ int   g_rowptr[NN + 1];
__device__ int   g_part[NN];
__device__ int   g_bsum[SCAN_NBLK];
__device__ int   g_is64;

// ---------------------------------------------------------------------------
// Zero counters + warp-parallel dtype detect (block 0, warp 0):
// int64 values < 2^31 ==> all odd int32 words zero. 32 parallel probes.
// ---------------------------------------------------------------------------
__global__ void k_zero(const int* __restrict__ raw, int n) {
    int i = blockIdx.x * blockDim.x + threadIdx.x;
    if (i < n) g_cnt[i] = 0;
    if (blockIdx.x == 0 && threadIdx.x < 32) {
        int w = raw[threadIdx.x * 2 + 1];                 // odd int32 words
        unsigned nz = __ballot_sync(0xFFFFFFFFu, w != 0);
        if (threadIdx.x == 0) g_is64 = (nz == 0u);
    }
}

// Parse raw edges -> int2, count in-degrees, record slot within dst's list.
// 2 edges per thread (16B loads).
__global__ void k_convert(const void* __restrict__ raw, int e) {
    int i = (blockIdx.x * blockDim.x + threadIdx.x) * 2;
    if (i >= e) return;
    int s0, d0, s1, d1;
    if (g_is64) {
        const longlong2* ps = (const longlong2*)raw;              // src pairs
        const longlong2* pd = (const longlong2*)((const long long*)raw + e);
        longlong2 sv = ps[i >> 1];
        longlong2 dv = pd[i >> 1];
        s0 = (int)sv.x; s1 = (int)sv.y;
        d0 = (int)dv.x; d1 = (int)dv.y;
    } else {
        const int2* ps = (const int2*)raw;
        const int2* pd = (const int2*)((const int*)raw + e);
        int2 sv = ps[i >> 1];
        int2 dv = pd[i >> 1];
        s0 = sv.x; s1 = sv.y;
        d0 = dv.x; d1 = dv.y;
    }
    s0 = min(max(s0, 0), NN - 1); d0 = min(max(d0, 0), NN - 1);
    g_edge[i] = make_int2(s0, d0);
    g_slot[i] = atomicAdd(&g_cnt[d0], 1);
    if (i + 1 < e) {
        s1 = min(max(s1, 0), NN - 1); d1 = min(max(d1, 0), NN - 1);
        g_edge[i + 1] = make_int2(s1, d1);
        g_slot[i + 1] = atomicAdd(&g_cnt[d1], 1);
    }
}

// ---------------------------------------------------------------------------
// Exclusive scan of g_cnt (3 kernels, proven); dis fused into pass 1.
// ---------------------------------------------------------------------------
__global__ void k_scan1(int n) {
    __shared__ int sh[SCAN_B];
    int i = blockIdx.x * SCAN_B + threadIdx.x;
    int v = (i < n) ? g_cnt[i] : 0;
    if (i < n) g_dis[i] = rsqrtf((float)(v + 1));          // +1 self-loop
    sh[threadIdx.x] = v;
    __syncthreads();
#pragma unroll
    for (int off = 1; off < SCAN_B; off <<= 1) {
        int t = (threadIdx.x >= off) ? sh[threadIdx.x - off] : 0;
        __syncthreads();
        sh[threadIdx.x] += t;
        __syncthreads();
    }
    if (i < n) g_part[i] = sh[threadIdx.x] - v;            // exclusive
    if (threadIdx.x == SCAN_B - 1) g_bsum[blockIdx.x] = sh[SCAN_B - 1];
}

// One block, 256 threads: shfl-based exclusive scan of block sums.
__global__ void k_scan2() {
    __shared__ int ws[8];
    int t = threadIdx.x;
    int lane = t & 31, w = t >> 5;
    int v = (t < SCAN_NBLK) ? g_bsum[t] : 0;               // SCAN_NBLK <= 256
    int inc = v;
#pragma unroll
    for (int off = 1; off < 32; off <<= 1) {
        int y = __shfl_up_sync(0xFFFFFFFFu, inc, off);
        if (lane >= off) inc += y;
    }
    if (lane == 31) ws[w] = inc;
    __syncthreads();
    if (t < 8) {
        int x = ws[t];
        int s = x;
#pragma unroll
        for (int off = 1; off < 8; off <<= 1) {
            int y = __shfl_up_sync(0x000000FFu, s, off);
            if (t >= off) s += y;
        }
        ws[t] = s - x;                                      // exclusive warp base
    }
    __syncthreads();
    if (t < SCAN_NBLK) g_bsum[t] = inc - v + ws[w];
}

__global__ void k_scan3(int n, int e) {
    int i = blockIdx.x * SCAN_B + threadIdx.x;
    if (i < n) g_rowptr[i] = g_part[i] + g_bsum[blockIdx.x];
    if (i == 0) g_rowptr[n] = e;
}

// ---------------------------------------------------------------------------
// CSR fill, atomic-free: position = rowptr[dst] + precomputed slot.
// ---------------------------------------------------------------------------
__global__ void k_fill(int e) {
    int i = blockIdx.x * blockDim.x + threadIdx.x;
    if (i >= e) return;
    int2 ed = g_edge[i];
    g_esrc[g_rowptr[ed.y] + g_slot[i]] = ed.x;
}

// ---------------------------------------------------------------------------
// Dense transform with pre-scale epilogue:
//   H[r,f] = ((relu?)(X[r,:]) @ W[:,f]) * dis[r]
// ---------------------------------------------------------------------------
template <int K, int F, bool RELU_IN>
__global__ void k_gemm(const float* __restrict__ X,
                       const float* __restrict__ W,
                       float* __restrict__ H, int n) {
    constexpr int G = F / 4;
    __shared__ float Ws[K * F];
    for (int i = threadIdx.x; i < K * F; i += blockDim.x) Ws[i] = W[i];
    __syncthreads();

    int tid = blockIdx.x * blockDim.x + threadIdx.x;
    int row = tid / G;
    int g   = tid % G;
    if (row >= n) return;

    const float* xr = X + (size_t)row * K;
    float4 acc = make_float4(0.f, 0.f, 0.f, 0.f);
#pragma unroll
    for (int k = 0; k < K; k++) {
        float xv = xr[k];
        if (RELU_IN) xv = fmaxf(xv, 0.f);
        float4 w = *reinterpret_cast<const float4*>(&Ws[k * F + g * 4]);
        acc.x = fmaf(xv, w.x, acc.x);
        acc.y = fmaf(xv, w.y, acc.y);
        acc.z = fmaf(xv, w.z, acc.z);
        acc.w = fmaf(xv, w.w, acc.w);
    }
    float ds = g_dis[row];
    acc.x *= ds; acc.y *= ds; acc.z *= ds; acc.w *= ds;
    *reinterpret_cast<float4*>(&H[(size_t)row * F + g * 4]) = acc;
}

// ---------------------------------------------------------------------------
// CSR gather-aggregate with factored normalization:
//   O[v,f] = b[f] + dis[v] * ( Hs[v,f] + sum_{s in list(v)} Hs[s,f] )
// unroll 4 for deeper gather MLP.
// ---------------------------------------------------------------------------
template <int F>
__global__ void k_aggcsr(const float* __restrict__ H,
                         const float* __restrict__ b,
                         float* __restrict__ O, int n) {
    constexpr int G = F / 4;
    int tid = blockIdx.x * blockDim.x + threadIdx.x;
    int node = tid / G;
    int g    = tid % G;
    if (node >= n) return;

    size_t o = (size_t)node * F + g * 4;
    float4 acc = *reinterpret_cast<const float4*>(&H[o]);   // self term (pre-scaled)

    int beg = g_rowptr[node];
    int end = g_rowptr[node + 1];
#pragma unroll 4
    for (int j = beg; j < end; j++) {
        int s = g_esrc[j];                          // broadcast across G threads
        float4 v = *reinterpret_cast<const float4*>(&H[(size_t)s * F + g * 4]);
        acc.x += v.x; acc.y += v.y; acc.z += v.z; acc.w += v.w;
    }
    float ds = g_dis[node];
    float4 bv = *reinterpret_cast<const float4*>(&b[g * 4]);
    float4 ov = make_float4(bv.x + acc.x * ds, bv.y + acc.y * ds,
                            bv.z + acc.z * ds, bv.w + acc.w * ds);
    *reinterpret_cast<float4*>(&O[o]) = ov;
}

// ---------------------------------------------------------------------------
// Launch (10 launches, single stream)
// ---------------------------------------------------------------------------
static inline int cdiv(long long a, int b) { return (int)((a + b - 1) / b); }

extern "C" void kernel_launch(void* const* d_in, const int* in_sizes, int n_in,
                              void* d_out, int out_size) {
    const float* x   = (const float*)d_in[0];
    const void*  ei  = d_in[1];
    const float* W1  = (const float*)d_in[2];
    const float* b1  = (const float*)d_in[3];
    const float* W2  = (const float*)d_in[4];
    const float* b2  = (const float*)d_in[5];
    float*       out = (float*)d_out;

    const int n = in_sizes[0] / IN_DIM;   // 100000
    const int e = in_sizes[1] / 2;        // 1600000

    float *h0, *out1, *h1;
    cudaGetSymbolAddress((void**)&h0,   g_h0);
    cudaGetSymbolAddress((void**)&out1, g_out1);
    cudaGetSymbolAddress((void**)&h1,   g_h1);

    const int T = 256;

    // CSR build
    k_zero   <<<cdiv(n, T), T>>>((const int*)ei, n);
    k_convert<<<cdiv(cdiv(e, 2), T), T>>>(ei, e);
    k_scan1  <<<SCAN_NBLK, SCAN_B>>>(n);
    k_scan2  <<<1, 256>>>();
    k_scan3  <<<SCAN_NBLK, SCAN_B>>>(n, e);
    k_fill   <<<cdiv(e, T), T>>>(e);

    // Layer 1
    k_gemm<IN_DIM, HID_DIM, false><<<cdiv((long long)n * (HID_DIM / 4), T), T>>>(x, W1, h0, n);
    k_aggcsr<HID_DIM><<<cdiv((long long)n * (HID_DIM / 4), T), T>>>(h0, b1, out1, n);

    // Layer 2
    k_gemm<HID_DIM, OUT_DIM, true><<<cdiv((long long)n * (OUT_DIM / 4), T), T>>>(out1, W2, h1, n);
    k_aggcsr<OUT_DIM><<<cdiv((long long)n * (OUT_DIM / 4), T), T>>>(h1, b2, out, n);
}

// round 16
// speedup vs baseline: 1.0429x; 1.0007x over previous
#include <cuda_runtime.h>

#define NN  100000
#define NE  1600000
#define IN_DIM  64
#define HID_DIM 48
#define OUT_DIM 32

#define SCAN_B 512
#define SCAN_NBLK ((NN + SCAN_B - 1) / SCAN_B)

// ---------------------------------------------------------------------------
// Scratch (device globals)
// ---------------------------------------------------------------------------
__device__ float g_h0  [(size_t)NN * HID_DIM];   // (x @ W1) * dis[row]   (pre-scaled)
__device__ float g_out1[(size_t)NN * HID_DIM];   // layer-1 output
__device__ float g_h1  [(size_t)NN * OUT_DIM];   // (relu(out1) @ W2) * dis[row]
__device__ float g_dis [NN];
__device__ int2  g_edge[NE];                     // parsed (src, dst)
__device__ int   g_slot[NE];                     // slot of edge within dst's list
__device__ int   g_esrc[NE];                     // CSR records: src only
__device__ int   g_cnt [NN];
__device__ int   g_rowptr[NN + 1];
__device__ int   g_part[NN];
__device__ int   g_bsum[SCAN_NBLK];
__device__ int   g_is64;

// ---------------------------------------------------------------------------
// Zero counters + warp-parallel dtype detect (block 0, warp 0):
// int64 values < 2^31 ==> all odd int32 words zero. 32 parallel probes.
// ---------------------------------------------------------------------------
__global__ void k_zero(const int* __restrict__ raw, int n) {
    int i = blockIdx.x * blockDim.x + threadIdx.x;
    if (i < n) g_cnt[i] = 0;
    if (blockIdx.x == 0 && threadIdx.x < 32) {
        int w = raw[threadIdx.x * 2 + 1];                 // odd int32 words
        unsigned nz = __ballot_sync(0xFFFFFFFFu, w != 0);
        if (threadIdx.x == 0) g_is64 = (nz == 0u);
    }
}

// Parse raw edges -> int2, count in-degrees, record slot within dst's list.
// 2 edges per thread (16B loads).
__global__ void k_convert(const void* __restrict__ raw, int e) {
    int i = (blockIdx.x * blockDim.x + threadIdx.x) * 2;
    if (i >= e) return;
    int s0, d0, s1, d1;
    if (g_is64) {
        const longlong2* ps = (const longlong2*)raw;              // src pairs
        const longlong2* pd = (const longlong2*)((const long long*)raw + e);
        longlong2 sv = ps[i >> 1];
        longlong2 dv = pd[i >> 1];
        s0 = (int)sv.x; s1 = (int)sv.y;
        d0 = (int)dv.x; d1 = (int)dv.y;
    } else {
        const int2* ps = (const int2*)raw;
        const int2* pd = (const int2*)((const int*)raw + e);
        int2 sv = ps[i >> 1];
        int2 dv = pd[i >> 1];
        s0 = sv.x; s1 = sv.y;
        d0 = dv.x; d1 = dv.y;
    }
    s0 = min(max(s0, 0), NN - 1); d0 = min(max(d0, 0), NN - 1);
    g_edge[i] = make_int2(s0, d0);
    g_slot[i] = atomicAdd(&g_cnt[d0], 1);
    if (i + 1 < e) {
        s1 = min(max(s1, 0), NN - 1); d1 = min(max(d1, 0), NN - 1);
        g_edge[i + 1] = make_int2(s1, d1);
        g_slot[i + 1] = atomicAdd(&g_cnt[d1], 1);
    }
}

// ---------------------------------------------------------------------------
// Exclusive scan of g_cnt (3 kernels, proven); dis fused into pass 1.
// ---------------------------------------------------------------------------
__global__ void k_scan1(int n) {
    __shared__ int sh[SCAN_B];
    int i = blockIdx.x * SCAN_B + threadIdx.x;
    int v = (i < n) ? g_cnt[i] : 0;
    if (i < n) g_dis[i] = rsqrtf((float)(v + 1));          // +1 self-loop
    sh[threadIdx.x] = v;
    __syncthreads();
#pragma unroll
    for (int off = 1; off < SCAN_B; off <<= 1) {
        int t = (threadIdx.x >= off) ? sh[threadIdx.x - off] : 0;
        __syncthreads();
        sh[threadIdx.x] += t;
        __syncthreads();
    }
    if (i < n) g_part[i] = sh[threadIdx.x] - v;            // exclusive
    if (threadIdx.x == SCAN_B - 1) g_bsum[blockIdx.x] = sh[SCAN_B - 1];
}

// One block, 256 threads: shfl-based exclusive scan of block sums.
__global__ void k_scan2() {
    __shared__ int ws[8];
    int t = threadIdx.x;
    int lane = t & 31, w = t >> 5;
    int v = (t < SCAN_NBLK) ? g_bsum[t] : 0;               // SCAN_NBLK <= 256
    int inc = v;
#pragma unroll
    for (int off = 1; off < 32; off <<= 1) {
        int y = __shfl_up_sync(0xFFFFFFFFu, inc, off);
        if (lane >= off) inc += y;
    }
    if (lane == 31) ws[w] = inc;
    __syncthreads();
    if (t < 8) {
        int x = ws[t];
        int s = x;
#pragma unroll
        for (int off = 1; off < 8; off <<= 1) {
            int y = __shfl_up_sync(0x000000FFu, s, off);
            if (t >= off) s += y;
        }
        ws[t] = s - x;                                      // exclusive warp base
    }
    __syncthreads();
    if (t < SCAN_NBLK) g_bsum[t] = inc - v + ws[w];
}

__global__ void k_scan3(int n, int e) {
    int i = blockIdx.x * SCAN_B + threadIdx.x;
    if (i < n) g_rowptr[i] = g_part[i] + g_bsum[blockIdx.x];
    if (i == 0) g_rowptr[n] = e;
}

// ---------------------------------------------------------------------------
// FUSED: CSR fill (blocks [0, fillB)) + layer-1 GEMM (blocks [fillB, ...)).
// The two tasks are data-independent; fusing them overlaps the scatter-bound
// fill with the FMA-bound transform in one launch (no stream machinery).
//   fill:  g_esrc[rowptr[dst] + slot] = src        (atomic-free)
//   gemm:  H[r,f] = (X[r,:] @ W[:,f]) * dis[r]
// ---------------------------------------------------------------------------
template <int K, int F>
__global__ void k_fill_gemm(const float* __restrict__ X,
                            const float* __restrict__ W,
                            float* __restrict__ H,
                            int n, int e, int fillB) {
    constexpr int G = F / 4;
    __shared__ float Ws[K * F];

    if (blockIdx.x < fillB) {
        // ---- fill role ----
        int i = blockIdx.x * blockDim.x + threadIdx.x;
        if (i < e) {
            int2 ed = g_edge[i];
            g_esrc[g_rowptr[ed.y] + g_slot[i]] = ed.x;
        }
        return;
    }

    // ---- gemm role ----
    for (int i = threadIdx.x; i < K * F; i += blockDim.x) Ws[i] = W[i];
    __syncthreads();

    int tid = (blockIdx.x - fillB) * blockDim.x + threadIdx.x;
    int row = tid / G;
    int g   = tid % G;
    if (row >= n) return;

    const float* xr = X + (size_t)row * K;
    float4 acc = make_float4(0.f, 0.f, 0.f, 0.f);
#pragma unroll
    for (int k = 0; k < K; k++) {
        float xv = xr[k];
        float4 w = *reinterpret_cast<const float4*>(&Ws[k * F + g * 4]);
        acc.x = fmaf(xv, w.x, acc.x);
        acc.y = fmaf(xv, w.y, acc.y);
        acc.z = fmaf(xv, w.z, acc.z);
        acc.w = fmaf(xv, w.w, acc.w);
    }
    float ds = g_dis[row];
    acc.x *= ds; acc.y *= ds; acc.z *= ds; acc.w *= ds;
    *reinterpret_cast<float4*>(&H[(size_t)row * F + g * 4]) = acc;
}

// ---------------------------------------------------------------------------
// Dense transform with pre-scale epilogue (layer 2):
//   H[r,f] = (relu(X[r,:]) @ W[:,f]) * dis[r]
// ---------------------------------------------------------------------------
template <int K, int F, bool RELU_IN>
__global__ void k_gemm(const float* __restrict__ X,
                       const float* __restrict__ W,
                       float* __restrict__ H, int n) {
    constexpr int G = F / 4;
    __shared__ float Ws[K * F];
    for (int i = threadIdx.x; i < K * F; i += blockDim.x) Ws[i] = W[i];
    __syncthreads();

    int tid = blockIdx.x * blockDim.x + threadIdx.x;
    int row = tid / G;
    int g   = tid % G;
    if (row >= n) return;

    const float* xr = X + (size_t)row * K;
    float4 acc = make_float4(0.f, 0.f, 0.f, 0.f);
#pragma unroll
    for (int k = 0; k < K; k++) {
        float xv = xr[k];
        if (RELU_IN) xv = fmaxf(xv, 0.f);
        float4 w = *reinterpret_cast<const float4*>(&Ws[k * F + g * 4]);
        acc.x = fmaf(xv, w.x, acc.x);
        acc.y = fmaf(xv, w.y, acc.y);
        acc.z = fmaf(xv, w.z, acc.z);
        acc.w = fmaf(xv, w.w, acc.w);
    }
    float ds = g_dis[row];
    acc.x *= ds; acc.y *= ds; acc.z *= ds; acc.w *= ds;
    *reinterpret_cast<float4*>(&H[(size_t)row * F + g * 4]) = acc;
}

// ---------------------------------------------------------------------------
// CSR gather-aggregate with factored normalization:
//   O[v,f] = b[f] + dis[v] * ( Hs[v,f] + sum_{s in list(v)} Hs[s,f] )
// unroll 4 for deeper gather MLP.
// ---------------------------------------------------------------------------
template <int F>
__global__ void k_aggcsr(const float* __restrict__ H,
                         const float* __restrict__ b,
                         float* __restrict__ O, int n) {
    constexpr int G = F / 4;
    int tid = blockIdx.x * blockDim.x + threadIdx.x;
    int node = tid / G;
    int g    = tid % G;
    if (node >= n) return;

    size_t o = (size_t)node * F + g * 4;
    float4 acc = *reinterpret_cast<const float4*>(&H[o]);   // self term (pre-scaled)

    int beg = g_rowptr[node];
    int end = g_rowptr[node + 1];
#pragma unroll 4
    for (int j = beg; j < end; j++) {
        int s = g_esrc[j];                          // broadcast across G threads
        float4 v = *reinterpret_cast<const float4*>(&H[(size_t)s * F + g * 4]);
        acc.x += v.x; acc.y += v.y; acc.z += v.z; acc.w += v.w;
    }
    float ds = g_dis[node];
    float4 bv = *reinterpret_cast<const float4*>(&b[g * 4]);
    float4 ov = make_float4(bv.x + acc.x * ds, bv.y + acc.y * ds,
                            bv.z + acc.z * ds, bv.w + acc.w * ds);
    *reinterpret_cast<float4*>(&O[o]) = ov;
}

// ---------------------------------------------------------------------------
// Launch (8 launches, single stream)
// ---------------------------------------------------------------------------
static inline int cdiv(long long a, int b) { return (int)((a + b - 1) / b); }

extern "C" void kernel_launch(void* const* d_in, const int* in_sizes, int n_in,
                              void* d_out, int out_size) {
    const float* x   = (const float*)d_in[0];
    const void*  ei  = d_in[1];
    const float* W1  = (const float*)d_in[2];
    const float* b1  = (const float*)d_in[3];
    const float* W2  = (const float*)d_in[4];
    const float* b2  = (const float*)d_in[5];
    float*       out = (float*)d_out;

    const int n = in_sizes[0] / IN_DIM;   // 100000
    const int e = in_sizes[1] / 2;        // 1600000

    float *h0, *out1, *h1;
    cudaGetSymbolAddress((void**)&h0,   g_h0);
    cudaGetSymbolAddress((void**)&out1, g_out1);
    cudaGetSymbolAddress((void**)&h1,   g_h1);

    const int T = 256;

    // CSR build
    k_zero   <<<cdiv(n, T), T>>>((const int*)ei, n);
    k_convert<<<cdiv(cdiv(e, 2), T), T>>>(ei, e);
    k_scan1  <<<SCAN_NBLK, SCAN_B>>>(n);
    k_scan2  <<<1, 256>>>();
    k_scan3  <<<SCAN_NBLK, SCAN_B>>>(n, e);

    // Fused: CSR fill + layer-1 GEMM (independent tasks, one launch)
    {
        int fillB = cdiv(e, T);
        int gemmB = cdiv((long long)n * (HID_DIM / 4), T);
        k_fill_gemm<IN_DIM, HID_DIM><<<fillB + gemmB, T>>>(x, W1, h0, n, e, fillB);
    }

    // Layer 1 aggregation
    k_aggcsr<HID_DIM><<<cdiv((long long)n * (HID_DIM / 4), T), T>>>(h0, b1, out1, n);

    // Layer 2
    k_gemm<HID_DIM, OUT_DIM, true><<<cdiv((long long)n * (OUT_DIM / 4), T), T>>>(out1, W2, h1, n);
    k_aggcsr<OUT_DIM><<<cdiv((long long)n * (OUT_DIM / 4), T), T>>>(h1, b2, out, n);
}